// round 12
// baseline (speedup 1.0000x reference)
#include <cuda_runtime.h>
#include <cuda_fp16.h>
#include <cstdint>

#define EMAX 131072
#define HID 256
#define TILE 128
#define THREADS 512
#define KF0 800            // 781 padded to 25 chunks of 32
#define KC 32
#define BN_EPS 1e-5f

// smem strides in HALVES — conflict-free ldmatrix row access
#define ASTRH 40
#define BSTRH 40
#define HSTRH 264

// smem byte offsets
#define OFFB_IDX  0          // 4 * 128 ints      = 2048
#define OFFB_BIAS 2048       // 256 floats        = 1024
#define OFFB_A    3072       // 2 * 128*40 halves = 20480
#define OFFB_B    23552      // 3 * 256*40 halves = 61440
#define OFFB_H    84992      // 128*264 halves    = 67584
#define SMEM_BYTES 152576    // -> 1 CTA/SM (512 thr = 16 warps, same as 2x256)

#define ABUFH (TILE * ASTRH)      // halves per A buffer
#define BBUFH (256 * BSTRH)       // halves per B buffer

static __device__ int    g_cnt[4];
static __device__ int    g_bucket[4 * EMAX];
static __device__ __align__(16) __half g_w0t[4 * HID * KF0];      // [br][n][kf]
static __device__ __align__(16) __half g_wht[4 * 3 * HID * HID];  // [br][l][n][k]
static __device__ float  g_biasf[4 * 4 * HID];                    // [br][layer][n]

__device__ __forceinline__ uint32_t smem_u32(const void* p) {
    uint32_t a;
    asm("{ .reg .u64 t; cvta.to.shared.u64 t, %1; cvt.u32.u64 %0, t; }" : "=r"(a) : "l"(p));
    return a;
}
__device__ __forceinline__ void cpa16(uint32_t dst, const void* src) {
    asm volatile("cp.async.cg.shared.global [%0], [%1], 16;" :: "r"(dst), "l"(src));
}
#define CPA_COMMIT() asm volatile("cp.async.commit_group;" ::: "memory")
#define CPA_WAIT0()  asm volatile("cp.async.wait_group 0;" ::: "memory")
#define CPA_WAIT1()  asm volatile("cp.async.wait_group 1;" ::: "memory")

__device__ __forceinline__ void ldsm4(uint32_t* r, uint32_t addr) {
    asm volatile("ldmatrix.sync.aligned.m8n8.x4.shared.b16 {%0,%1,%2,%3}, [%4];"
                 : "=r"(r[0]), "=r"(r[1]), "=r"(r[2]), "=r"(r[3]) : "r"(addr));
}
__device__ __forceinline__ void mma16(float* d, const uint32_t* a, const uint32_t* b) {
    asm volatile(
        "mma.sync.aligned.m16n8k16.row.col.f32.f16.f16.f32 "
        "{%0,%1,%2,%3}, {%4,%5,%6,%7}, {%8,%9}, {%0,%1,%2,%3};"
        : "+f"(d[0]), "+f"(d[1]), "+f"(d[2]), "+f"(d[3])
        : "r"(a[0]), "r"(a[1]), "r"(a[2]), "r"(a[3]), "r"(b[0]), "r"(b[1]));
}
__device__ __forceinline__ void red2(float* p, float x, float y) {
    asm volatile("red.global.add.v2.f32 [%0], {%1,%2};" :: "l"(p), "f"(x), "f"(y) : "memory");
}
__device__ __forceinline__ uint32_t h2u(float x, float y) {
    __half2 h = __floats2half2_rn(x, y);
    return *reinterpret_cast<uint32_t*>(&h);
}

// ---------------- prep kernels ----------------
__global__ void reset_kernel() { if (threadIdx.x < 4) g_cnt[threadIdx.x] = 0; }

__global__ void bucket_kernel(const int* __restrict__ edx_ij, const int* __restrict__ edx_jk,
                              const int* __restrict__ nei_ptr, int E) {
    int e = blockIdx.x * blockDim.x + threadIdx.x;
    int lane = threadIdx.x & 31;
    bool valid = (e < E);
    int nei = nei_ptr[0];
    int br = 0;
    if (valid) {
        int mij = (edx_ij[e] < nei) ? 1 : 0;
        int mjk = (edx_jk[e] < nei) ? 1 : 0;
        br = ((mij ^ 1) << 1) | (mjk ^ 1);
    }
    #pragma unroll
    for (int b = 0; b < 4; b++) {
        unsigned m = __ballot_sync(0xffffffffu, valid && br == b);
        if (!m) continue;
        int leader = __ffs(m) - 1;
        int base = 0;
        if (lane == leader) base = atomicAdd(&g_cnt[b], __popc(m));
        base = __shfl_sync(0xffffffffu, base, leader);
        if (valid && br == b) {
            int rank = __popc(m & ((1u << lane) - 1u));
            g_bucket[b * EMAX + base + rank] = e;
        }
    }
}

#define N_W0 (4 * HID * KF0)
#define N_WH (4 * 3 * HID * HID)
#define N_BI (4 * 4 * HID)
__global__ void prep_all(const float* __restrict__ W0, const float* __restrict__ Wh,
                         const float* __restrict__ b0, const float* __restrict__ bh,
                         const float* __restrict__ gamma, const float* __restrict__ beta,
                         const float* __restrict__ rmean, const float* __restrict__ rvar,
                         int din) {
    int idx = blockIdx.x * blockDim.x + threadIdx.x;
    if (idx < N_W0) {
        int kf = idx % KF0, n = (idx / KF0) % HID, br = idx / (KF0 * HID);
        float sc = gamma[(br * 4 + 0) * HID + n] * rsqrtf(rvar[(br * 4 + 0) * HID + n] + BN_EPS);
        float v = 0.f;
        if (kf < din) v = W0[((size_t)br * din + kf) * HID + n] * sc;
        g_w0t[idx] = __float2half_rn(v);
        return;
    }
    int j = idx - N_W0;
    if (j < N_WH) {
        int k = j % HID, n = (j / HID) % HID;
        int l = (j / (HID * HID)) % 3, br = j / (3 * HID * HID);
        float sc = gamma[(br * 4 + l + 1) * HID + n] *
                   rsqrtf(rvar[(br * 4 + l + 1) * HID + n] + BN_EPS);
        float v = Wh[(((size_t)(br * 3 + l)) * HID + k) * HID + n] * sc;
        g_wht[j] = __float2half_rn(v);
        return;
    }
    j -= N_WH;
    if (j < N_BI) {
        int n = j % HID, l = (j / HID) % 4, br = j / (4 * HID);
        int gi = (br * 4 + l) * HID + n;
        float sc = gamma[gi] * rsqrtf(rvar[gi] + BN_EPS);
        float b = (l == 0) ? b0[br * HID + n] : bh[((size_t)(br * 3) + (l - 1)) * HID + n];
        g_biasf[j] = (b - rmean[gi]) * sc + beta[gi];
    }
}

// ------- main fused MLP kernel (fp16 mma, ldmatrix, TILE=128, 512 thr, 1 CTA/SM) ----
__global__ __launch_bounds__(THREADS, 1)
void mlp_mma_kernel(const float* __restrict__ nf, const float* __restrict__ geo,
                    const int* __restrict__ eidx, const float* __restrict__ att,
                    float* __restrict__ out, int E, int G) {
    extern __shared__ char smc[];
    int* s_i = (int*)(smc + OFFB_IDX);
    int* s_j = s_i + TILE;
    int* s_k = s_j + TILE;
    int* s_e = s_k + TILE;
    float* bias_s = (float*)(smc + OFFB_BIAS);
    __half* Asm = (__half*)(smc + OFFB_A);
    __half* Hsm = (__half*)(smc + OFFB_H);

    // 1D tile grid: find branch by scanning tile counts
    int t = blockIdx.x, br = -1, tstart = 0, accum = 0;
    #pragma unroll
    for (int b = 0; b < 4; b++) {
        int tb = (g_cnt[b] + TILE - 1) / TILE;
        if (br < 0 && t < accum + tb) { br = b; tstart = (t - accum) * TILE; }
        accum += tb;
    }
    if (br < 0) return;
    const int cnt = g_cnt[br];
    const int ne = min(TILE, cnt - tstart);

    const int tid = threadIdx.x;
    const int warp = tid >> 5, lane = tid & 31;
    const int mbase = (warp & 1) * 64;        // warp M block (two halves of 128 rows)
    const int nbase = (warp >> 1) * 32;       // warp N block (8 groups of 32)
    const uint32_t asm_u = smem_u32(smc + OFFB_A);
    const uint32_t bsm_u = smem_u32(smc + OFFB_B);
    const uint32_t hsm_u = smem_u32(smc + OFFB_H);

    // ldmatrix per-thread row/k selectors (validated mapping)
    const int lmA  = lane & 15;
    const int lmAk = (lane & 16) ? 8 : 0;
    const int lmBr = (lane & 7) + ((lane & 16) ? 8 : 0);
    const int lmBk = (lane & 8) ? 8 : 0;
    const int t4 = lane >> 2, tm4 = lane & 3;

    if (tid < 3 * TILE) {
        int which = tid >> 7, r = tid & (TILE - 1);
        int tt = min(r, ne - 1);              // pad tile with last valid edge
        int e = g_bucket[br * EMAX + tstart + tt];
        if (which == 0) { s_e[r] = e; s_i[r] = eidx[e]; }
        else if (which == 1) s_j[r] = eidx[E + e];
        else s_k[r] = eidx[2 * E + e];
    }
    __syncthreads();

    const int arow = tid >> 2, aq = tid & 3;  // cooperative A staging coords (128 rows)
    float acc[4][4][4];

    // block-cooperative COALESCED B staging into buffer (c % 3): 2 cpa16 per thread
    #define STAGE_B(Wsrc, wstr, c) do {                                          \
        const __half* _s0 = (Wsrc) + (size_t)(c) * KC;                           \
        const uint32_t _d0 = bsm_u + ((c) % 3) * (BBUFH * 2);                    \
        _Pragma("unroll")                                                        \
        for (int p = 0; p < 2; p++) {                                            \
            int idx = p * THREADS + tid;                                         \
            int row = idx >> 2, sub = idx & 3;                                   \
            cpa16(_d0 + row * (BSTRH * 2) + sub * 16,                            \
                  _s0 + (size_t)row * (wstr) + sub * 8);                         \
        }                                                                        \
        CPA_COMMIT();                                                            \
    } while (0)

    // ldmatrix + mma for one chunk (2 k-steps of 16); warp covers rows mbase..mbase+63
    #define COMPUTE(a_u, astr, koff, b_u) do {                                   \
        _Pragma("unroll")                                                        \
        for (int s = 0; s < 2; s++) {                                            \
            uint32_t a[4][4], bb[2][4];                                          \
            _Pragma("unroll")                                                    \
            for (int m = 0; m < 4; m++)                                          \
                ldsm4(a[m], (a_u) + ((mbase + m * 16 + lmA) * (astr) + (koff) + s * 16 + lmAk) * 2); \
            _Pragma("unroll")                                                    \
            for (int p = 0; p < 2; p++)                                          \
                ldsm4(bb[p], (b_u) + ((nbase + p * 16 + lmBr) * BSTRH + s * 16 + lmBk) * 2); \
            _Pragma("unroll")                                                    \
            for (int m = 0; m < 4; m++) {                                        \
                _Pragma("unroll")                                                \
                for (int p = 0; p < 2; p++) {                                    \
                    mma16(acc[m][2 * p],     a[m], &bb[p][0]);                   \
                    mma16(acc[m][2 * p + 1], a[m], &bb[p][2]);                   \
                }                                                                \
            }                                                                    \
        }                                                                        \
    } while (0)

    #define ZERO_ACC() do {                                                      \
        _Pragma("unroll")                                                        \
        for (int m = 0; m < 4; m++)                                              \
            _Pragma("unroll")                                                    \
            for (int n = 0; n < 4; n++)                                          \
                _Pragma("unroll")                                                \
                for (int q = 0; q < 4; q++) acc[m][n][q] = 0.f;                  \
    } while (0)

    for (int l = 0; l < 4; l++) {
        const int nch = (l == 0) ? (KF0 / KC) : (HID / KC);   // 25 or 8
        const __half* Wsrc = (l == 0) ? (g_w0t + (size_t)br * HID * KF0)
                                      : (g_wht + ((size_t)(br * 3) + (l - 1)) * HID * HID);
        const int wstr = (l == 0) ? KF0 : HID;

        ZERO_ACC();
        if (tid < HID) bias_s[tid] = g_biasf[((size_t)(br * 4) + l) * HID + tid];

        // ---- prologue: stage B chunks 0 and 1; A chunk 0 (l0) ----
        STAGE_B(Wsrc, wstr, 0);
        STAGE_B(Wsrc, wstr, 1);
        if (l == 0) {   // A chunk 0: node-i feats 0..31, rn-rounded
            const float* src = nf + (size_t)s_i[arow] * HID + aq * 8;
            float4 v0 = *(const float4*)(src);
            float4 v1 = *(const float4*)(src + 4);
            uint4 u = { h2u(v0.x, v0.y), h2u(v0.z, v0.w), h2u(v1.x, v1.y), h2u(v1.z, v1.w) };
            *(uint4*)(Asm + arow * ASTRH + aq * 8) = u;
        }
        CPA_WAIT1();                          // B chunk 0 complete (chunk 1 may fly)
        __syncthreads();

        for (int c = 0; c < nch; c++) {
            const bool s2 = (c + 2 < nch);
            const bool a1 = (c + 1 < nch);

            // ---- kick off B chunk c+2 ----
            if (s2) STAGE_B(Wsrc, wstr, c + 2);

            // ---- A gather prefetch for chunk c+1 (layer 0) ----
            float4 pa0, pa1;
            float pg[8];
            bool geo_chunk = false;
            if (l == 0 && a1) {
                const int cn = c + 1;
                if (cn < 24) {
                    const int* sidx = (cn < 8) ? s_i : (cn < 16) ? s_j : s_k;
                    const float* src = nf + (size_t)sidx[arow] * HID + (cn & 7) * 32 + aq * 8;
                    pa0 = *(const float4*)(src);
                    pa1 = *(const float4*)(src + 4);
                } else {
                    geo_chunk = true;
                    #pragma unroll
                    for (int p = 0; p < 8; p++) {
                        int idx = p * THREADS + tid;
                        int row = idx >> 5, fi = idx & 31;
                        pg[p] = (fi < G) ? geo[(size_t)s_e[row] * G + fi] : 0.f;
                    }
                }
            }

            // ---- compute chunk c ----
            if (l == 0) COMPUTE(asm_u + (c & 1) * (ABUFH * 2), ASTRH, 0,
                                bsm_u + (c % 3) * (BBUFH * 2));
            else        COMPUTE(hsm_u, HSTRH, c * KC, bsm_u + (c % 3) * (BBUFH * 2));

            // ---- store A chunk c+1 (layer 0) ----
            if (l == 0 && a1) {
                __half* dst = Asm + ((c + 1) & 1) * ABUFH;
                if (!geo_chunk) {
                    uint4 u = { h2u(pa0.x, pa0.y), h2u(pa0.z, pa0.w),
                                h2u(pa1.x, pa1.y), h2u(pa1.z, pa1.w) };
                    *(uint4*)(dst + arow * ASTRH + aq * 8) = u;
                } else {
                    #pragma unroll
                    for (int p = 0; p < 8; p++) {
                        int idx = p * THREADS + tid;
                        int row = idx >> 5, fi = idx & 31;
                        dst[row * ASTRH + fi] = __float2half_rn(pg[p]);
                    }
                }
            }

            // ---- ensure B chunk c+1 landed ----
            if (s2)      CPA_WAIT1();
            else if (a1) CPA_WAIT0();
            __syncthreads();
        }

        // ---- epilogue ----
        if (l < 3) {
            // bias + ReLU -> fp16 rn -> Hsm (next layer's A)
            #pragma unroll
            for (int m = 0; m < 4; m++) {
                const int r0 = mbase + m * 16 + t4;
                #pragma unroll
                for (int n = 0; n < 4; n++) {
                    const int c0 = nbase + n * 8 + 2 * tm4;
                    const float b0v = bias_s[c0], b1v = bias_s[c0 + 1];
                    *(uint32_t*)(Hsm + r0 * HSTRH + c0) =
                        h2u(fmaxf(acc[m][n][0] + b0v, 0.f), fmaxf(acc[m][n][1] + b1v, 0.f));
                    *(uint32_t*)(Hsm + (r0 + 8) * HSTRH + c0) =
                        h2u(fmaxf(acc[m][n][2] + b0v, 0.f), fmaxf(acc[m][n][3] + b1v, 0.f));
                }
            }
            __syncthreads();
        } else {
            // final: bias + ReLU (leaky identity on >=0), * att, fp32 scatter to out[i]
            const float attv = __ldg(att + br);
            #pragma unroll
            for (int m = 0; m < 4; m++) {
                const int r0 = mbase + m * 16 + t4;
                const int r1 = r0 + 8;
                float* o0 = (r0 < ne) ? (out + (size_t)s_i[r0] * HID) : 0;
                float* o1 = (r1 < ne) ? (out + (size_t)s_i[r1] * HID) : 0;
                #pragma unroll
                for (int n = 0; n < 4; n++) {
                    const int c0 = nbase + n * 8 + 2 * tm4;
                    const float b0v = bias_s[c0], b1v = bias_s[c0 + 1];
                    if (o0) red2(o0 + c0, fmaxf(acc[m][n][0] + b0v, 0.f) * attv,
                                          fmaxf(acc[m][n][1] + b1v, 0.f) * attv);
                    if (o1) red2(o1 + c0, fmaxf(acc[m][n][2] + b0v, 0.f) * attv,
                                          fmaxf(acc[m][n][3] + b1v, 0.f) * attv);
                }
            }
        }
    }
}

// ---------------- launch ----------------
extern "C" void kernel_launch(void* const* d_in, const int* in_sizes, int n_in,
                              void* d_out, int out_size) {
    const float* nf     = (const float*)d_in[0];
    const float* geo    = (const float*)d_in[1];
    const int*   eidx   = (const int*)d_in[2];
    const int*   edx_ij = (const int*)d_in[3];
    const int*   edx_jk = (const int*)d_in[4];
    const float* att    = (const float*)d_in[5];
    const float* W0     = (const float*)d_in[6];
    const float* b0     = (const float*)d_in[7];
    const float* Wh     = (const float*)d_in[8];
    const float* bh     = (const float*)d_in[9];
    const float* gamma  = (const float*)d_in[10];
    const float* beta   = (const float*)d_in[11];
    const float* rmean  = (const float*)d_in[12];
    const float* rvar   = (const float*)d_in[13];
    const int*   nei    = (const int*)d_in[14];

    int E = in_sizes[3];
    int G = in_sizes[1] / E;
    int din = 3 * HID + G;
    float* out = (float*)d_out;

    cudaMemsetAsync(out, 0, (size_t)out_size * sizeof(float), 0);
    reset_kernel<<<1, 32>>>();
    bucket_kernel<<<(E + 255) / 256, 256>>>(edx_ij, edx_jk, nei, E);

    int nprep = N_W0 + N_WH + N_BI;
    prep_all<<<(nprep + 255) / 256, 256>>>(W0, Wh, b0, bh, gamma, beta, rmean, rvar, din);

    cudaFuncSetAttribute(mlp_mma_kernel, cudaFuncAttributeMaxDynamicSharedMemorySize,
                         SMEM_BYTES);
    int ntiles = (E + TILE - 1) / TILE + 4;   // upper bound over per-branch tile sums
    mlp_mma_kernel<<<ntiles, THREADS, SMEM_BYTES>>>(nf, geo, eidx, att, out, E, G);
}

// round 14
// speedup vs baseline: 1.0836x; 1.0836x over previous
#include <cuda_runtime.h>
#include <cuda_fp16.h>
#include <cstdint>

#define EMAX 131072
#define HID 256
#define TILE 64
#define KF0 800            // 781 padded to 25 chunks of 32
#define KC 32
#define BN_EPS 1e-5f

// smem strides in HALVES — conflict-free ldmatrix row access
#define ASTRH 40
#define BSTRH 40
#define HSTRH 264

// smem byte offsets
#define OFFB_IDX  0          // 4 * 64 ints = 1024
#define OFFB_BIAS 1024       // 256 floats = 1024
#define OFFB_A    2048       // 2 * 64*40 halves   = 10240
#define OFFB_B    12288      // 3 * 256*40 halves  = 61440
#define OFFB_H    73728      // 64*264 halves      = 33792
#define SMEM_BYTES 107520    // -> 2 CTAs/SM

#define ABUFH (TILE * ASTRH)      // halves per A buffer
#define BBUFH (256 * BSTRH)       // halves per B buffer

static __device__ int    g_cnt[4];
static __device__ int    g_bucket[4 * EMAX];
static __device__ __align__(16) __half g_w0t[4 * HID * KF0];      // [br][n][kf]
static __device__ __align__(16) __half g_wht[4 * 3 * HID * HID];  // [br][l][n][k]
static __device__ float  g_biasf[4 * 4 * HID];                    // [br][layer][n]

__device__ __forceinline__ uint32_t smem_u32(const void* p) {
    uint32_t a;
    asm("{ .reg .u64 t; cvta.to.shared.u64 t, %1; cvt.u32.u64 %0, t; }" : "=r"(a) : "l"(p));
    return a;
}
__device__ __forceinline__ void cpa16(uint32_t dst, const void* src) {
    asm volatile("cp.async.cg.shared.global [%0], [%1], 16;" :: "r"(dst), "l"(src));
}
#define CPA_COMMIT() asm volatile("cp.async.commit_group;" ::: "memory")
#define CPA_WAIT0()  asm volatile("cp.async.wait_group 0;" ::: "memory")
#define CPA_WAIT1()  asm volatile("cp.async.wait_group 1;" ::: "memory")

__device__ __forceinline__ void ldsm4(uint32_t* r, uint32_t addr) {
    asm volatile("ldmatrix.sync.aligned.m8n8.x4.shared.b16 {%0,%1,%2,%3}, [%4];"
                 : "=r"(r[0]), "=r"(r[1]), "=r"(r[2]), "=r"(r[3]) : "r"(addr));
}
__device__ __forceinline__ void mma16(float* d, const uint32_t* a, const uint32_t* b) {
    asm volatile(
        "mma.sync.aligned.m16n8k16.row.col.f32.f16.f16.f32 "
        "{%0,%1,%2,%3}, {%4,%5,%6,%7}, {%8,%9}, {%0,%1,%2,%3};"
        : "+f"(d[0]), "+f"(d[1]), "+f"(d[2]), "+f"(d[3])
        : "r"(a[0]), "r"(a[1]), "r"(a[2]), "r"(a[3]), "r"(b[0]), "r"(b[1]));
}
__device__ __forceinline__ void red2(float* p, float x, float y) {
    asm volatile("red.global.add.v2.f32 [%0], {%1,%2};" :: "l"(p), "f"(x), "f"(y) : "memory");
}
__device__ __forceinline__ uint32_t h2u(float x, float y) {
    __half2 h = __floats2half2_rn(x, y);
    return *reinterpret_cast<uint32_t*>(&h);
}

// ---------------- prep kernels ----------------
__global__ void reset_kernel() { if (threadIdx.x < 4) g_cnt[threadIdx.x] = 0; }

__global__ void bucket_kernel(const int* __restrict__ edx_ij, const int* __restrict__ edx_jk,
                              const int* __restrict__ nei_ptr, int E) {
    int e = blockIdx.x * blockDim.x + threadIdx.x;
    int lane = threadIdx.x & 31;
    bool valid = (e < E);
    int nei = nei_ptr[0];
    int br = 0;
    if (valid) {
        int mij = (edx_ij[e] < nei) ? 1 : 0;
        int mjk = (edx_jk[e] < nei) ? 1 : 0;
        br = ((mij ^ 1) << 1) | (mjk ^ 1);
    }
    #pragma unroll
    for (int b = 0; b < 4; b++) {
        unsigned m = __ballot_sync(0xffffffffu, valid && br == b);
        if (!m) continue;
        int leader = __ffs(m) - 1;
        int base = 0;
        if (lane == leader) base = atomicAdd(&g_cnt[b], __popc(m));
        base = __shfl_sync(0xffffffffu, base, leader);
        if (valid && br == b) {
            int rank = __popc(m & ((1u << lane) - 1u));
            g_bucket[b * EMAX + base + rank] = e;
        }
    }
}

#define N_W0 (4 * HID * KF0)
#define N_WH (4 * 3 * HID * HID)
#define N_BI (4 * 4 * HID)
__global__ void prep_all(const float* __restrict__ W0, const float* __restrict__ Wh,
                         const float* __restrict__ b0, const float* __restrict__ bh,
                         const float* __restrict__ gamma, const float* __restrict__ beta,
                         const float* __restrict__ rmean, const float* __restrict__ rvar,
                         int din) {
    int idx = blockIdx.x * blockDim.x + threadIdx.x;
    if (idx < N_W0) {
        int kf = idx % KF0, n = (idx / KF0) % HID, br = idx / (KF0 * HID);
        float sc = gamma[(br * 4 + 0) * HID + n] * rsqrtf(rvar[(br * 4 + 0) * HID + n] + BN_EPS);
        float v = 0.f;
        if (kf < din) v = W0[((size_t)br * din + kf) * HID + n] * sc;
        g_w0t[idx] = __float2half_rn(v);
        return;
    }
    int j = idx - N_W0;
    if (j < N_WH) {
        int k = j % HID, n = (j / HID) % HID;
        int l = (j / (HID * HID)) % 3, br = j / (3 * HID * HID);
        float sc = gamma[(br * 4 + l + 1) * HID + n] *
                   rsqrtf(rvar[(br * 4 + l + 1) * HID + n] + BN_EPS);
        float v = Wh[(((size_t)(br * 3 + l)) * HID + k) * HID + n] * sc;
        g_wht[j] = __float2half_rn(v);
        return;
    }
    j -= N_WH;
    if (j < N_BI) {
        int n = j % HID, l = (j / HID) % 4, br = j / (4 * HID);
        int gi = (br * 4 + l) * HID + n;
        float sc = gamma[gi] * rsqrtf(rvar[gi] + BN_EPS);
        float b = (l == 0) ? b0[br * HID + n] : bh[((size_t)(br * 3) + (l - 1)) * HID + n];
        g_biasf[j] = (b - rmean[gi]) * sc + beta[gi];
    }
}

// ---- main fused MLP kernel (fp16 mma, ldmatrix; hidden layers: warp-private B) ----
__global__ __launch_bounds__(256, 2)
void mlp_mma_kernel(const float* __restrict__ nf, const float* __restrict__ geo,
                    const int* __restrict__ eidx, const float* __restrict__ att,
                    float* __restrict__ out, int E, int G) {
    extern __shared__ char smc[];
    int* s_i = (int*)(smc + OFFB_IDX);
    int* s_j = s_i + TILE;
    int* s_k = s_j + TILE;
    int* s_e = s_k + TILE;
    float* bias_s = (float*)(smc + OFFB_BIAS);
    __half* Asm = (__half*)(smc + OFFB_A);
    __half* Hsm = (__half*)(smc + OFFB_H);

    // 1D tile grid: find branch by scanning tile counts
    int t = blockIdx.x, br = -1, tstart = 0, accum = 0;
    #pragma unroll
    for (int b = 0; b < 4; b++) {
        int tb = (g_cnt[b] + TILE - 1) / TILE;
        if (br < 0 && t < accum + tb) { br = b; tstart = (t - accum) * TILE; }
        accum += tb;
    }
    if (br < 0) return;
    const int cnt = g_cnt[br];
    const int ne = min(TILE, cnt - tstart);

    const int tid = threadIdx.x;
    const int warp = tid >> 5, lane = tid & 31;
    const int nbase = warp * 32;              // this warp's N block (M shared: 64 rows)
    const uint32_t asm_u = smem_u32(smc + OFFB_A);
    const uint32_t bsm_u = smem_u32(smc + OFFB_B);
    const uint32_t hsm_u = smem_u32(smc + OFFB_H);

    // ldmatrix per-thread row/k selectors (validated mapping)
    const int lmA  = lane & 15;
    const int lmAk = (lane & 16) ? 8 : 0;
    const int lmBr = (lane & 7) + ((lane & 16) ? 8 : 0);
    const int lmBk = (lane & 8) ? 8 : 0;
    const int t4 = lane >> 2, tm4 = lane & 3;

    if (tid < 3 * TILE) {
        int which = tid >> 6, r = tid & (TILE - 1);
        int tt = min(r, ne - 1);              // pad tile with last valid edge
        int e = g_bucket[br * EMAX + tstart + tt];
        if (which == 0) { s_e[r] = e; s_i[r] = eidx[e]; }
        else if (which == 1) s_j[r] = eidx[E + e];
        else s_k[r] = eidx[2 * E + e];
    }
    __syncthreads();

    const int arow = tid >> 2, aq = tid & 3;  // cooperative A staging coords
    float acc[4][4][4];

    // block-cooperative COALESCED B staging into buffer (c % 3) — layer 0 only
    #define STAGE_B(Wsrc, wstr, c) do {                                          \
        const __half* _s0 = (Wsrc) + (size_t)(c) * KC;                           \
        const uint32_t _d0 = bsm_u + ((c) % 3) * (BBUFH * 2);                    \
        _Pragma("unroll")                                                        \
        for (int p = 0; p < 4; p++) {                                            \
            int idx = p * 256 + tid;                                             \
            int row = idx >> 2, sub = idx & 3;                                   \
            cpa16(_d0 + row * (BSTRH * 2) + sub * 16,                            \
                  _s0 + (size_t)row * (wstr) + sub * 8);                         \
        }                                                                        \
        CPA_COMMIT();                                                            \
    } while (0)

    // WARP-PRIVATE coalesced B staging: warp stages its own 32 n-rows,
    // 4 lanes per row (each cpa16 instr = 8 rows x contiguous 64B).
    #define STAGE_BW(Wsrc, c) do {                                               \
        const __half* _s0 = (Wsrc) + (size_t)(c) * KC;                           \
        const uint32_t _d0 = bsm_u + ((c) % 3) * (BBUFH * 2);                    \
        _Pragma("unroll")                                                        \
        for (int q = 0; q < 4; q++) {                                            \
            int row = nbase + q * 8 + t4;                                        \
            cpa16(_d0 + row * (BSTRH * 2) + tm4 * 16,                            \
                  _s0 + (size_t)row * HID + tm4 * 8);                            \
        }                                                                        \
        CPA_COMMIT();                                                            \
    } while (0)

    // ldmatrix + mma for one chunk (2 k-steps of 16)
    #define COMPUTE(a_u, astr, koff, b_u) do {                                   \
        _Pragma("unroll")                                                        \
        for (int s = 0; s < 2; s++) {                                            \
            uint32_t a[4][4], bb[2][4];                                          \
            _Pragma("unroll")                                                    \
            for (int m = 0; m < 4; m++)                                          \
                ldsm4(a[m], (a_u) + ((m * 16 + lmA) * (astr) + (koff) + s * 16 + lmAk) * 2); \
            _Pragma("unroll")                                                    \
            for (int p = 0; p < 2; p++)                                          \
                ldsm4(bb[p], (b_u) + ((nbase + p * 16 + lmBr) * BSTRH + s * 16 + lmBk) * 2); \
            _Pragma("unroll")                                                    \
            for (int m = 0; m < 4; m++) {                                        \
                _Pragma("unroll")                                                \
                for (int p = 0; p < 2; p++) {                                    \
                    mma16(acc[m][2 * p],     a[m], &bb[p][0]);                   \
                    mma16(acc[m][2 * p + 1], a[m], &bb[p][2]);                   \
                }                                                                \
            }                                                                    \
        }                                                                        \
    } while (0)

    #define ZERO_ACC() do {                                                      \
        _Pragma("unroll")                                                        \
        for (int m = 0; m < 4; m++)                                              \
            _Pragma("unroll")                                                    \
            for (int n = 0; n < 4; n++)                                          \
                _Pragma("unroll")                                                \
                for (int q = 0; q < 4; q++) acc[m][n][q] = 0.f;                  \
    } while (0)

    // ================= layer 0 (block-cooperative: A is shared) =================
    {
        const __half* Wsrc = g_w0t + (size_t)br * HID * KF0;
        ZERO_ACC();
        bias_s[tid] = g_biasf[(size_t)(br * 4) * HID + tid];

        STAGE_B(Wsrc, KF0, 0);
        STAGE_B(Wsrc, KF0, 1);
        {   // A chunk 0: node-i feats 0..31, rn-rounded
            const float* src = nf + (size_t)s_i[arow] * HID + aq * 8;
            float4 v0 = *(const float4*)(src);
            float4 v1 = *(const float4*)(src + 4);
            uint4 u = { h2u(v0.x, v0.y), h2u(v0.z, v0.w), h2u(v1.x, v1.y), h2u(v1.z, v1.w) };
            *(uint4*)(Asm + arow * ASTRH + aq * 8) = u;
        }
        CPA_WAIT1();
        __syncthreads();

        for (int c = 0; c < 25; c++) {
            const bool s2 = (c + 2 < 25);
            const bool a1 = (c + 1 < 25);

            if (s2) STAGE_B(Wsrc, KF0, c + 2);

            float4 pa0, pa1;
            float pg[8];
            bool geo_chunk = false;
            if (a1) {
                const int cn = c + 1;
                if (cn < 24) {
                    const int* sidx = (cn < 8) ? s_i : (cn < 16) ? s_j : s_k;
                    const float* src = nf + (size_t)sidx[arow] * HID + (cn & 7) * 32 + aq * 8;
                    pa0 = *(const float4*)(src);
                    pa1 = *(const float4*)(src + 4);
                } else {
                    geo_chunk = true;
                    #pragma unroll
                    for (int p = 0; p < 8; p++) {
                        int idx = p * 256 + tid;
                        int row = idx >> 5, fi = idx & 31;
                        pg[p] = (fi < G) ? geo[(size_t)s_e[row] * G + fi] : 0.f;
                    }
                }
            }

            COMPUTE(asm_u + (c & 1) * (ABUFH * 2), ASTRH, 0, bsm_u + (c % 3) * (BBUFH * 2));

            if (a1) {
                __half* dst = Asm + ((c + 1) & 1) * ABUFH;
                if (!geo_chunk) {
                    uint4 u = { h2u(pa0.x, pa0.y), h2u(pa0.z, pa0.w),
                                h2u(pa1.x, pa1.y), h2u(pa1.z, pa1.w) };
                    *(uint4*)(dst + arow * ASTRH + aq * 8) = u;
                } else {
                    #pragma unroll
                    for (int p = 0; p < 8; p++) {
                        int idx = p * 256 + tid;
                        int row = idx >> 5, fi = idx & 31;
                        dst[row * ASTRH + fi] = __float2half_rn(pg[p]);
                    }
                }
            }

            if (s2)      CPA_WAIT1();
            else if (a1) CPA_WAIT0();
            __syncthreads();
        }

        // epilogue: bias + ReLU -> fp16 rn -> Hsm (warp-private n-columns)
        #pragma unroll
        for (int m = 0; m < 4; m++) {
            const int r0 = m * 16 + t4;
            #pragma unroll
            for (int n = 0; n < 4; n++) {
                const int c0 = nbase + n * 8 + 2 * tm4;
                const float b0v = bias_s[c0], b1v = bias_s[c0 + 1];
                *(uint32_t*)(Hsm + r0 * HSTRH + c0) =
                    h2u(fmaxf(acc[m][n][0] + b0v, 0.f), fmaxf(acc[m][n][1] + b1v, 0.f));
                *(uint32_t*)(Hsm + (r0 + 8) * HSTRH + c0) =
                    h2u(fmaxf(acc[m][n][2] + b0v, 0.f), fmaxf(acc[m][n][3] + b1v, 0.f));
            }
        }
        __syncthreads();          // H fully written before hidden layers read it
    }

    // ====== hidden layers: warp-private B pipeline, __syncwarp only ======
    for (int l = 1; l < 4; l++) {
        const __half* Wsrc = g_wht + ((size_t)(br * 3) + (l - 1)) * HID * HID;
        ZERO_ACC();
        bias_s[nbase + lane] = g_biasf[((size_t)(br * 4) + l) * HID + nbase + lane];

        STAGE_BW(Wsrc, 0);
        STAGE_BW(Wsrc, 1);
        CPA_WAIT1();
        __syncwarp();

        for (int c = 0; c < 8; c++) {
            if (c + 2 < 8) STAGE_BW(Wsrc, c + 2);
            COMPUTE(hsm_u, HSTRH, c * KC, bsm_u + (c % 3) * (BBUFH * 2));
            if (c + 2 < 8)      CPA_WAIT1();
            else if (c + 1 < 8) CPA_WAIT0();
            __syncwarp();
        }

        if (l < 3) {
            __syncthreads();      // all warps done reading Hsm before overwrite
            #pragma unroll
            for (int m = 0; m < 4; m++) {
                const int r0 = m * 16 + t4;
                #pragma unroll
                for (int n = 0; n < 4; n++) {
                    const int c0 = nbase + n * 8 + 2 * tm4;
                    const float b0v = bias_s[c0], b1v = bias_s[c0 + 1];
                    *(uint32_t*)(Hsm + r0 * HSTRH + c0) =
                        h2u(fmaxf(acc[m][n][0] + b0v, 0.f), fmaxf(acc[m][n][1] + b1v, 0.f));
                    *(uint32_t*)(Hsm + (r0 + 8) * HSTRH + c0) =
                        h2u(fmaxf(acc[m][n][2] + b0v, 0.f), fmaxf(acc[m][n][3] + b1v, 0.f));
                }
            }
            __syncthreads();      // writes visible before next layer reads
        } else {
            // final: bias + ReLU (leaky identity on >=0), * att, fp32 scatter to out[i]
            const float attv = __ldg(att + br);
            #pragma unroll
            for (int m = 0; m < 4; m++) {
                const int r0 = m * 16 + t4;
                const int r1 = r0 + 8;
                float* o0 = (r0 < ne) ? (out + (size_t)s_i[r0] * HID) : 0;
                float* o1 = (r1 < ne) ? (out + (size_t)s_i[r1] * HID) : 0;
                #pragma unroll
                for (int n = 0; n < 4; n++) {
                    const int c0 = nbase + n * 8 + 2 * tm4;
                    const float b0v = bias_s[c0], b1v = bias_s[c0 + 1];
                    if (o0) red2(o0 + c0, fmaxf(acc[m][n][0] + b0v, 0.f) * attv,
                                          fmaxf(acc[m][n][1] + b1v, 0.f) * attv);
                    if (o1) red2(o1 + c0, fmaxf(acc[m][n][2] + b0v, 0.f) * attv,
                                          fmaxf(acc[m][n][3] + b1v, 0.f) * attv);
                }
            }
        }
    }
}

// ---------------- launch ----------------
extern "C" void kernel_launch(void* const* d_in, const int* in_sizes, int n_in,
                              void* d_out, int out_size) {
    const float* nf     = (const float*)d_in[0];
    const float* geo    = (const float*)d_in[1];
    const int*   eidx   = (const int*)d_in[2];
    const int*   edx_ij = (const int*)d_in[3];
    const int*   edx_jk = (const int*)d_in[4];
    const float* att    = (const float*)d_in[5];
    const float* W0     = (const float*)d_in[6];
    const float* b0     = (const float*)d_in[7];
    const float* Wh     = (const float*)d_in[8];
    const float* bh     = (const float*)d_in[9];
    const float* gamma  = (const float*)d_in[10];
    const float* beta   = (const float*)d_in[11];
    const float* rmean  = (const float*)d_in[12];
    const float* rvar   = (const float*)d_in[13];
    const int*   nei    = (const int*)d_in[14];

    int E = in_sizes[3];
    int G = in_sizes[1] / E;
    int din = 3 * HID + G;
    float* out = (float*)d_out;

    cudaMemsetAsync(out, 0, (size_t)out_size * sizeof(float), 0);
    reset_kernel<<<1, 32>>>();
    bucket_kernel<<<(E + 255) / 256, 256>>>(edx_ij, edx_jk, nei, E);

    int nprep = N_W0 + N_WH + N_BI;
    prep_all<<<(nprep + 255) / 256, 256>>>(W0, Wh, b0, bh, gamma, beta, rmean, rvar, din);

    cudaFuncSetAttribute(mlp_mma_kernel, cudaFuncAttributeMaxDynamicSharedMemorySize,
                         SMEM_BYTES);
    int ntiles = (E + TILE - 1) / TILE + 4;   // upper bound over per-branch tile sums
    mlp_mma_kernel<<<ntiles, 256, SMEM_BYTES>>>(nf, geo, eidx, att, out, E, G);
}